// round 14
// baseline (speedup 1.0000x reference)
#include <cuda_runtime.h>
#include <math.h>
#include <stdint.h>

// Problem constants
#define NB 64
#define NT 256
#define NC 53
#define NH 64
#define NA 128
#define NG 192
#define NCC 2809          // C*C
#define LDB_ 132          // row stride for A-wide smem buffers (mult of 4 for float4)
#define LDH_ 68           // row stride for h_gru buffer
#define LDG_ 194          // padded row stride for transposed w_hh
#define NTHR 512

// smem layout (float offsets)
#define OFF_H     0        // 27*64 = 1728
#define OFF_HG    1728     // 53*68 = 3604
#define OFF_B1    5332     // 53*132 = 6996
#define OFF_B2    12328    // 6996
#define OFF_TR    19324    // 1432
#define OFF_FNC   20756    // 1432
#define OFF_GB    22188    // 1432
#define OFF_W     23620    // 4 slots * 4096 = 16384 (16B aligned)
#define OFF_WHH   40004    // 64*194 = 12416
#define OFF_ALPHA 52420    // 192
#define OFF_BETA  52612    // 192
#define OFF_BHH   52804    // 192
#define OFF_MB0   52996    // 128
#define OFF_MB1   53124    // 128
#define OFF_MB2   53252    // 128
#define OFF_PW    53380    // 64
#define OFF_XROW  53444    // 56
#define OFF_RED   53500    // 16
#define OFF_PSUM  53516    // 2
#define OFF_SC    53518    // 2
#define SMEM_FLOATS 53520
#define SMEM_BYTES (SMEM_FLOATS * 4)   // 214,080 B

#define SLOT_STRIDE 4096   // 32 h * 128 j floats per chunk (contiguous)

// Output offsets (floats) in d_out
#define OUT_LOGITS 0
#define OUT_FNC    128
#define OUT_MIX    179904ULL
#define OUT_PRED   46202560ULL
#define OUT_X      47067520ULL

// Classifier scratch (device globals: allocation-free rule)
__device__ float g_z1[16384 * 1404]; // 92 MB
__device__ float g_z2[16384 * 702];  // 46 MB
// K-pair-interleaved MLP weights: q0(64x128), q1, q2, k0, k1, k2
// element (h, j) of layer at [hp*256 + 2*j + (h&1)], hp = h>>1
__device__ float g_wt[81920];

typedef unsigned long long u64;

__device__ __forceinline__ float sigm(float v) { return 1.0f / (1.0f + expf(-v)); }

__device__ __forceinline__ u64 pack2(float lo, float hi) {
    u64 r; asm("mov.b64 %0,{%1,%2};" : "=l"(r) : "f"(lo), "f"(hi)); return r;
}
__device__ __forceinline__ u64 bcast2(float v) { return pack2(v, v); }
__device__ __forceinline__ u64 fma2(u64 a, u64 b, u64 c) {
    u64 d; asm("fma.rn.f32x2 %0,%1,%2,%3;" : "=l"(d) : "l"(a), "l"(b), "l"(c)); return d;
}
__device__ __forceinline__ float2 unpack2(u64 v) {
    float2 f; asm("mov.b64 {%0,%1},%2;" : "=f"(f.x), "=f"(f.y) : "l"(v)); return f;
}
__device__ __forceinline__ u64 lds2(const float* p) { return *(const u64*)p; }

// ---- cluster helpers ----
__device__ __forceinline__ void cluster_sync_() {
    asm volatile("barrier.cluster.arrive.aligned;" ::: "memory");
    asm volatile("barrier.cluster.wait.aligned;" ::: "memory");
}
__device__ __forceinline__ uint32_t smem_u32(const void* p) {
    uint32_t a;
    asm("{ .reg .u64 t; cvta.to.shared.u64 t, %1; cvt.u32.u64 %0, t; }" : "=r"(a) : "l"(p));
    return a;
}
__device__ __forceinline__ uint32_t mapa32(uint32_t a, uint32_t r) {
    uint32_t o; asm("mapa.shared::cluster.u32 %0,%1,%2;" : "=r"(o) : "r"(a), "r"(r)); return o;
}
__device__ __forceinline__ u64 ld_dsmem64(uint32_t a) {
    u64 v; asm volatile("ld.shared::cluster.b64 %0, [%1];" : "=l"(v) : "r"(a)); return v;
}
__device__ __forceinline__ float ld_dsmem32(uint32_t a) {
    float v; asm volatile("ld.shared::cluster.f32 %0, [%1];" : "=f"(v) : "r"(a)); return v;
}

// ---- cp.async helpers ----
__device__ __forceinline__ void cp_async16(uint32_t dst, const void* src) {
    asm volatile("cp.async.cg.shared.global [%0], [%1], 16;" :: "r"(dst), "l"(src));
}
__device__ __forceinline__ void cp_commit() {
    asm volatile("cp.async.commit_group;" ::: "memory");
}
template<int N> __device__ __forceinline__ void cp_wait() {
    asm volatile("cp.async.wait_group %0;" :: "n"(N) : "memory");
}

// Copy one 4096-float (16KB) contiguous weight chunk into slot.
__device__ __forceinline__ void issue_chunk(uint32_t wb, const float* src, int slot, int tid) {
    uint32_t dst0 = wb + (uint32_t)(OFF_W + slot * SLOT_STRIDE) * 4u;
#pragma unroll
    for (int j = 0; j < 2; ++j) {
        int k = tid + j * NTHR;           // 0..1023 16B units
        cp_async16(dst0 + (uint32_t)(k * 16), (const char*)src + k * 16);
    }
    cp_commit();
}

// Accumulate 32 h-values of a chunk in `slot`, K-packed f32x2.
// Thread tile: 7 rows (rbase..rbase+6, clamped) x 2 cols (jb, jb+1).
__device__ __forceinline__ void mlp_chunk(
    const float* sw, int slot, int in_off, int ldi, int h0,
    int jb, int rbase, u64 (&acc)[7][2])
{
    const float* wb_ = &sw[OFF_W + slot * SLOT_STRIDE + 2 * jb];
#pragma unroll
    for (int m = 0; m < 8; ++m) {
        float4 w40 = *(const float4*)(wb_ + (2 * m) * 256);       // h-pair (4m,4m+1)
        float4 w41 = *(const float4*)(wb_ + (2 * m + 1) * 256);   // h-pair (4m+2,4m+3)
        u64 w00 = lds2((const float*)&w40);
        u64 w01 = lds2(((const float*)&w40) + 2);
        u64 w10 = lds2((const float*)&w41);
        u64 w11 = lds2(((const float*)&w41) + 2);
        const float* inp = &sw[in_off + h0 + 4 * m];
#pragma unroll
        for (int u = 0; u < 7; ++u) {
            int r = rbase + u; if (r >= NC) r = 0;   // clamped garbage, never stored
            float4 iv = *(const float4*)(inp + r * ldi);
            u64 i01 = lds2((const float*)&iv);
            u64 i23 = lds2(((const float*)&iv) + 2);
            acc[u][0] = fma2(i01, w00, acc[u][0]);
            acc[u][1] = fma2(i01, w01, acc[u][1]);
            acc[u][0] = fma2(i23, w10, acc[u][0]);
            acc[u][1] = fma2(i23, w11, acc[u][1]);
        }
    }
}

__device__ __forceinline__ void mlp_zero(u64 (&acc)[7][2]) {
#pragma unroll
    for (int u = 0; u < 7; ++u) { acc[u][0] = 0ULL; acc[u][1] = 0ULL; }
}

__device__ __forceinline__ void mlp_store(
    float* sw, int out_off, int jb, int rbase, bool do_relu,
    u64 (&acc)[7][2], const float* bias)
{
    float b0 = bias[jb], b1 = bias[jb + 1];
#pragma unroll
    for (int u = 0; u < 7; ++u) {
        int r = rbase + u;
        if (r >= NC) break;
        float2 p0 = unpack2(acc[u][0]);
        float2 p1 = unpack2(acc[u][1]);
        float v0 = p0.x + p0.y + b0;
        float v1 = p1.x + p1.y + b1;
        if (do_relu) { v0 = fmaxf(v0, 0.0f); v1 = fmaxf(v1, 0.0f); }
        *(float2*)&sw[out_off + r * LDB_ + jb] = make_float2(v0, v1);
    }
}

// ---- prep: K-pair-interleave MLP weights into g_wt ----
__global__ void prep_wt(
    const float* __restrict__ q_w0, const float* __restrict__ q_w1, const float* __restrict__ q_w2,
    const float* __restrict__ k_w0, const float* __restrict__ k_w1, const float* __restrict__ k_w2)
{
    int idx = blockIdx.x * blockDim.x + threadIdx.x;
    if (idx >= 81920) return;
    const float* src; int off, Kin;
    if      (idx < 8192)  { src = q_w0; off = 0;     Kin = 64;  }
    else if (idx < 24576) { src = q_w1; off = 8192;  Kin = 128; }
    else if (idx < 40960) { src = q_w2; off = 24576; Kin = 128; }
    else if (idx < 49152) { src = k_w0; off = 40960; Kin = 64;  }
    else if (idx < 65536) { src = k_w1; off = 49152; Kin = 128; }
    else                  { src = k_w2; off = 65536; Kin = 128; }
    int l = idx - off;
    int hp = l >> 8, rem = l & 255;
    int j = rem >> 1, par = rem & 1;
    int h = 2 * hp + par;
    g_wt[idx] = src[j * Kin + h];
}

// Persistent recurrence: cluster of 2 CTAs per batch. 128 CTAs x 512 threads.
__global__ __launch_bounds__(NTHR, 1) __cluster_dims__(2, 1, 1)
void rec_kernel(
    const float* __restrict__ x,
    const float* __restrict__ w_emb, const float* __restrict__ b_emb,
    const float* __restrict__ w_ih, const float* __restrict__ w_hh,
    const float* __restrict__ b_ih, const float* __restrict__ b_hh,
    const float* __restrict__ q_b0, const float* __restrict__ q_b1, const float* __restrict__ q_b2,
    const float* __restrict__ k_b0, const float* __restrict__ k_b1, const float* __restrict__ k_b2,
    const float* __restrict__ gate_bias,
    const float* __restrict__ pred_w, const float* __restrict__ pred_b,
    float* __restrict__ out_fnc, float* __restrict__ out_mix, float* __restrict__ out_pred)
{
    extern __shared__ float sw[];
    const int tid = threadIdx.x;
    const int rank = blockIdx.x & 1;
    const int b = blockIdx.x >> 1;

    const int base = rank ? 27 : 0;
    const int cnt  = rank ? 26 : 27;
    const int baseP = rank ? 0 : 27;
    const int cntP  = rank ? 27 : 26;

    const uint32_t mybase = smem_u32(sw);
    const uint32_t peerbase = mapa32(mybase, (uint32_t)(rank ^ 1));
    const uint32_t wb = mybase;

    const int wid = tid >> 5, lane = tid & 31;

    // Interleaved weight bases for this rank's MLP path
    const float* WT  = rank ? (g_wt + 40960) : g_wt;
    const float* L0s = WT;            // 64 h rows
    const float* L1s = WT + 8192;     // 128 h rows
    const float* L2s = WT + 24576;    // 128 h rows

    const float* B0p = rank ? k_b0 : q_b0;
    const float* B1p = rank ? k_b1 : q_b1;
    const float* B2p = rank ? k_b2 : q_b2;

    // MLP thread mapping (warp grid 4j x 4r; lanes 16j x 2r)
    const int jb_mlp = 32 * (wid & 3) + 2 * (lane & 15);
    const int rbase_mlp = 7 * ((wid >> 2) * 2 + (lane >> 4));   // {0,7,...,49}

    // GRU mapping (warp grid 2j x 8r; lanes 16j x 2r)
    const int jg2_gru = 32 * (wid & 1) + 2 * (lane & 15);
    const int rgrp_gru = (wid >> 1) * 2 + (lane >> 4);          // 0..15

    // ---- one-time init ----
    if (tid < NG) {
        float a = 0.0f, be = 0.0f;
        for (int e = 0; e < NH; ++e) {
            float w = w_ih[tid * NH + e];
            a = fmaf(w, w_emb[e], a);
            be = fmaf(w, b_emb[e], be);
        }
        sw[OFF_ALPHA + tid] = a;
        sw[OFF_BETA + tid] = be + b_ih[tid];
        sw[OFF_BHH + tid] = b_hh[tid];
    }
    if (tid < NA) {
        sw[OFF_MB0 + tid] = B0p[tid];
        sw[OFF_MB1 + tid] = B1p[tid];
        sw[OFF_MB2 + tid] = B2p[tid];
    }
    if (tid < NH) sw[OFF_PW + tid] = pred_w[tid];
    if (tid < NC) sw[OFF_XROW + tid] = x[(size_t)b * NT * NC + tid];   // t = 0
    for (int idx = tid; idx < NG * NH; idx += NTHR) {
        int g = idx >> 6, hh = idx & 63;
        sw[OFF_WHH + hh * LDG_ + g] = w_hh[idx];
    }
    const int nhalf = cnt * NC;
    for (int i = tid; i < nhalf; i += NTHR) {
        sw[OFF_GB + i] = gate_bias[base * NC + i];
        sw[OFF_FNC + i] = 0.0f;
    }
    for (int i = tid; i < 27 * NH; i += NTHR) sw[OFF_H + i] = 0.0f;
    const float predb = pred_b[0];
    __syncthreads();

    for (int t = 0; t < NT; ++t) {
        // ---- prefetch next x row (register; staged to smem in gate phase) ----
        float xpref = 0.0f;
        if (t + 1 < NT && tid < NC)
            xpref = x[((size_t)b * NT + t + 1) * NC + tid];

        // ---- prefetch L0 weight chunks 0,1 (overlap with GRU) ----
        issue_chunk(wb, L0s,        0, tid);   // seq 0 -> slot 0
        issue_chunk(wb, L0s + 4096, 1, tid);   // seq 1 -> slot 1

        // ---- GRU on own half rows (dedup warp grid 2j x 8r) ----
        {
            const int jg2 = jg2_gru;
            const int rl0 = rgrp_gru;
            const bool has1 = (rgrp_gru + 16) < cnt;
            const int rl1 = has1 ? rgrp_gru + 16 : 0;
            u64 ar[2], az[2], an[2];
            {
                u64 br = lds2(&sw[OFF_BHH + jg2]);
                u64 bz = lds2(&sw[OFF_BHH + 64 + jg2]);
                u64 bn = lds2(&sw[OFF_BHH + 128 + jg2]);
                ar[0] = br; ar[1] = br;
                az[0] = bz; az[1] = bz;
                an[0] = bn; an[1] = bn;
            }
#pragma unroll 4
            for (int hh = 0; hh < NH; ++hh) {
                u64 p0 = bcast2(sw[OFF_H + rl0 * NH + hh]);
                u64 p1 = bcast2(sw[OFF_H + rl1 * NH + hh]);
                const float* wr = &sw[OFF_WHH + hh * LDG_ + jg2];
                u64 wrv = lds2(wr);
                u64 wzv = lds2(wr + 64);
                u64 wnv = lds2(wr + 128);
                ar[0] = fma2(p0, wrv, ar[0]); az[0] = fma2(p0, wzv, az[0]); an[0] = fma2(p0, wnv, an[0]);
                ar[1] = fma2(p1, wrv, ar[1]); az[1] = fma2(p1, wzv, az[1]); an[1] = fma2(p1, wnv, an[1]);
            }
#pragma unroll
            for (int u = 0; u < 2; ++u) {
                if (u == 1 && !has1) break;
                int rl = u ? rl1 : rl0;
                int rgl = base + rl;
                float xv = sw[OFF_XROW + rgl];
                float2 Ar = unpack2(ar[u]);
                float2 Az = unpack2(az[u]);
                float2 An = unpack2(an[u]);
#pragma unroll
                for (int e = 0; e < 2; ++e) {
                    int j = jg2 + e;
                    float arx = e ? Ar.y : Ar.x;
                    float azx = e ? Az.y : Az.x;
                    float anx = e ? An.y : An.x;
                    float gir = fmaf(xv, sw[OFF_ALPHA + j],       sw[OFF_BETA + j]);
                    float giz = fmaf(xv, sw[OFF_ALPHA + 64 + j],  sw[OFF_BETA + 64 + j]);
                    float gin = fmaf(xv, sw[OFF_ALPHA + 128 + j], sw[OFF_BETA + 128 + j]);
                    float rr = sigm(gir + arx);
                    float zz = sigm(giz + azx);
                    float nn = tanhf(gin + rr * anx);
                    sw[OFF_HG + rgl * LDH_ + j] = (1.0f - zz) * nn + zz * sw[OFF_H + rl * NH + j];
                }
            }
        }
        // sync #1: both halves of hg written; copy peer half
        cluster_sync_();
        {
            const uint32_t off = (uint32_t)(OFF_HG + baseP * LDH_) * 4u;
            const int n2 = cntP * (LDH_ / 2);
            for (int i = tid; i < n2; i += NTHR) {
                u64 v = ld_dsmem64(peerbase + off + 8u * (uint32_t)i);
                *(u64*)&sw[OFF_HG + baseP * LDH_ + 2 * i] = v;
            }
        }
        __syncthreads();

        // ---- own MLP: pipelined weight streaming, 10 chunks, 4-slot ring ----
        {
            u64 acc[7][2];

            // L0: seqs 0,1 (slots 0,1); in = HG (ld LDH_)
            mlp_zero(acc);
            cp_wait<1>(); __syncthreads();
            issue_chunk(wb, L1s + 0 * 4096, 2, tid);           // seq 2
            mlp_chunk(sw, 0, OFF_HG, LDH_, 0, jb_mlp, rbase_mlp, acc);
            cp_wait<1>(); __syncthreads();
            issue_chunk(wb, L1s + 1 * 4096, 3, tid);           // seq 3
            mlp_chunk(sw, 1, OFF_HG, LDH_, 32, jb_mlp, rbase_mlp, acc);
            mlp_store(sw, OFF_B1, jb_mlp, rbase_mlp, true, acc, &sw[OFF_MB0]);

            // L1: seqs 2..5 (slots 2,3,0,1); in = B1
            mlp_zero(acc);
            cp_wait<1>(); __syncthreads();                     // also orders B1 writes
            issue_chunk(wb, L1s + 2 * 4096, 0, tid);           // seq 4
            mlp_chunk(sw, 2, OFF_B1, LDB_, 0, jb_mlp, rbase_mlp, acc);
            cp_wait<1>(); __syncthreads();
            issue_chunk(wb, L1s + 3 * 4096, 1, tid);           // seq 5
            mlp_chunk(sw, 3, OFF_B1, LDB_, 32, jb_mlp, rbase_mlp, acc);
            cp_wait<1>(); __syncthreads();
            issue_chunk(wb, L2s + 0 * 4096, 2, tid);           // seq 6
            mlp_chunk(sw, 0, OFF_B1, LDB_, 64, jb_mlp, rbase_mlp, acc);
            cp_wait<1>(); __syncthreads();
            issue_chunk(wb, L2s + 1 * 4096, 3, tid);           // seq 7
            mlp_chunk(sw, 1, OFF_B1, LDB_, 96, jb_mlp, rbase_mlp, acc);
            mlp_store(sw, OFF_B2, jb_mlp, rbase_mlp, true, acc, &sw[OFF_MB1]);

            // L2: seqs 6..9 (slots 2,3,0,1); in = B2, out = B1, no relu
            mlp_zero(acc);
            cp_wait<1>(); __syncthreads();                     // also orders B2 writes
            issue_chunk(wb, L2s + 2 * 4096, 0, tid);           // seq 8
            mlp_chunk(sw, 2, OFF_B2, LDB_, 0, jb_mlp, rbase_mlp, acc);
            cp_wait<1>(); __syncthreads();
            issue_chunk(wb, L2s + 3 * 4096, 1, tid);           // seq 9
            mlp_chunk(sw, 3, OFF_B2, LDB_, 32, jb_mlp, rbase_mlp, acc);
            cp_wait<1>(); __syncthreads();
            mlp_chunk(sw, 0, OFF_B2, LDB_, 64, jb_mlp, rbase_mlp, acc);
            cp_wait<0>(); __syncthreads();
            mlp_chunk(sw, 1, OFF_B2, LDB_, 96, jb_mlp, rbase_mlp, acc);
            mlp_store(sw, OFF_B1, jb_mlp, rbase_mlp, false, acc, &sw[OFF_MB2]);
        }

        // sync #2: peer's final output ready in its B1; copy to local B2
        cluster_sync_();
        {
            const uint32_t off = (uint32_t)OFF_B1 * 4u;
            const int n2 = (NC * LDB_) / 2;  // 3498
            for (int i = tid; i < n2; i += NTHR) {
                u64 v = ld_dsmem64(peerbase + off + 8u * (uint32_t)i);
                *(u64*)&sw[OFF_B2 + 2 * i] = v;
            }
        }
        __syncthreads();

        // ---- transfer rows (own half): q[c,:] . k[d,:] over 128 (1r x 4d) ----
        {
            const int qoff = rank ? OFF_B2 : OFF_B1;
            const int koff = rank ? OFF_B1 : OFF_B2;
            const int dg = tid & 15;
            const int ry = tid >> 4;             // 0..31
            const bool rv = ry < cnt;
            const int rl = rv ? ry : 0;
            int dc[4]; bool dv[4];
#pragma unroll
            for (int v = 0; v < 4; ++v) { int d = dg + 16 * v; dv[v] = d < NC; dc[v] = dv[v] ? d : 0; }
            u64 acc[4];
#pragma unroll
            for (int v = 0; v < 4; ++v) acc[v] = 0ULL;
            const float* qrow = &sw[qoff + (base + rl) * LDB_];
#pragma unroll 4
            for (int i = 0; i < NA; i += 2) {
                u64 q0 = lds2(qrow + i);
#pragma unroll
                for (int v = 0; v < 4; ++v) {
                    u64 kv = lds2(&sw[koff + dc[v] * LDB_ + i]);
                    acc[v] = fma2(q0, kv, acc[v]);
                }
            }
            if (rv) {
#pragma unroll
                for (int v = 0; v < 4; ++v) if (dv[v]) {
                    float2 p = unpack2(acc[v]);
                    sw[OFF_TR + rl * NC + dc[v]] = p.x + p.y;
                }
            }
        }
        __syncthreads();

        // ---- Frobenius norm: local partial, exchange scalar ----
        {
            float s = 0.0f;
            for (int i = tid; i < nhalf; i += NTHR) { float v = sw[OFF_TR + i]; s = fmaf(v, v, s); }
#pragma unroll
            for (int o = 16; o; o >>= 1) s += __shfl_xor_sync(0xffffffffu, s, o);
            if ((tid & 31) == 0) sw[OFF_RED + (tid >> 5)] = s;
            __syncthreads();
            if (tid == 0) {
                float tot = 0.0f;
                for (int w = 0; w < 16; ++w) tot += sw[OFF_RED + w];
                sw[OFF_PSUM] = tot;
            }
        }
        cluster_sync_();
        if (tid == 0) {
            float peer = ld_dsmem32(peerbase + (uint32_t)OFF_PSUM * 4u);
            sw[OFF_SC] = 1.0f / sqrtf(sw[OFF_PSUM] + peer);
        }
        __syncthreads();

        // ---- normalize, gate, accumulate FNC, write mix; stage next x row ----
        {
            const float rn = sw[OFF_SC];
            float* mixp = out_mix + ((size_t)b * NT + t) * NCC + base * NC;
            for (int i = tid; i < nhalf; i += NTHR) {
                float v = sw[OFF_TR + i] * rn;
                float g = sigm(fabsf(v) + sw[OFF_GB + i]);
                v *= g;
                sw[OFF_TR + i] = v;
                sw[OFF_FNC + i] += v;
                mixp[i] = v;
            }
            if (t + 1 < NT && tid < NC) sw[OFF_XROW + tid] = xpref;
        }
        __syncthreads();

        // ---- h_new (own half rows) = transfer @ h_gru(full) (32 pairs x 2r) ----
        {
            const int hx2 = (tid & 31) * 2;
            const int ry = tid >> 5;             // 0..15
            const int rl0 = ry;
            const bool h1 = (ry + 16) < cnt;
            const int rl1 = h1 ? ry + 16 : 0;
            u64 acc0 = 0ULL, acc1 = 0ULL;
#pragma unroll 4
            for (int d = 0; d < NC; ++d) {
                u64 hv = lds2(&sw[OFF_HG + d * LDH_ + hx2]);
                u64 t0 = bcast2(sw[OFF_TR + rl0 * NC + d]);
                u64 t1 = bcast2(sw[OFF_TR + rl1 * NC + d]);
                acc0 = fma2(t0, hv, acc0);
                acc1 = fma2(t1, hv, acc1);
            }
            *(float2*)&sw[OFF_H + rl0 * NH + hx2] = unpack2(acc0);
            if (h1) *(float2*)&sw[OFF_H + rl1 * NH + hx2] = unpack2(acc1);
        }
        __syncthreads();

        // ---- predicted (own half rows, t < T-1) ----
        if (t < NT - 1 && tid < cnt) {
            float a = predb;
            for (int hh = 0; hh < NH; ++hh) a = fmaf(sw[OFF_H + tid * NH + hh], sw[OFF_PW + hh], a);
            out_pred[((size_t)b * (NT - 1) + t) * NC + base + tid] = a;
        }
    }

    // ---- mean_FNC (own half rows) ----
    for (int i = tid; i < nhalf; i += NTHR)
        out_fnc[(size_t)b * NCC + base * NC + i] = sw[OFF_FNC + i] * (1.0f / 256.0f);
}

// Tiled fp32 GEMM with packed f32x2 over M-row pairs (near roofline)
#define LDAS_ 132
__global__ __launch_bounds__(256) void gemm_relu(
    const float* __restrict__ A, const float* __restrict__ W,
    const float* __restrict__ bias, float* __restrict__ Cmat,
    int M, int N, int K, int do_relu)
{
    __shared__ float As[16 * LDAS_];
    __shared__ float Ws[16][65];
    const int m0 = blockIdx.y * 128;
    const int n0 = blockIdx.x * 64;
    const int tid = threadIdx.x;
    const int tx = tid & 15, ty = tid >> 4;
    u64 acc[4][4];
#pragma unroll
    for (int u = 0; u < 4; ++u)
#pragma unroll
        for (int v = 0; v < 4; ++v) acc[u][v] = 0ULL;

    for (int k0 = 0; k0 < K; k0 += 16) {
#pragma unroll
        for (int l = 0; l < 8; ++l) {
            int idx = tid + l * 256;
            int mi = idx >> 4, kk = idx & 15;
            int k = k0 + kk;
            As[kk * LDAS_ + mi] = (k < K) ? A[(size_t)(m0 + mi) * K + k] : 0.0f;
        }
#pragma unroll
        for (int l = 0; l < 4; ++l) {
            int idx = tid + l * 256;
            int ni = idx >> 4, kk = idx & 15;
            int k = k0 + kk, n = n0 + ni;
            Ws[kk][ni] = (k < K && n < N) ? W[(size_t)n * K + k] : 0.0f;
        }
        __syncthreads();
#pragma unroll
        for (int kk = 0; kk < 16; ++kk) {
            u64 a2[4], w2[4];
#pragma unroll
            for (int u = 0; u < 4; ++u) a2[u] = lds2(&As[kk * LDAS_ + 2 * ty + 32 * u]);
#pragma unroll
            for (int v = 0; v < 4; ++v) w2[v] = bcast2(Ws[kk][tx + 16 * v]);
#pragma unroll
            for (int u = 0; u < 4; ++u)
#pragma unroll
                for (int v = 0; v < 4; ++v) acc[u][v] = fma2(a2[u], w2[v], acc[u][v]);
        }
        __syncthreads();
    }
#pragma unroll
    for (int u = 0; u < 4; ++u) {
        int row0 = m0 + 2 * ty + 32 * u;
#pragma unroll
        for (int v = 0; v < 4; ++v) {
            int col = n0 + tx + 16 * v;
            if (col < N) {
                float2 p = unpack2(acc[u][v]);
                float bb = bias[col];
                float v0 = p.x + bb, v1 = p.y + bb;
                if (do_relu) { v0 = fmaxf(v0, 0.0f); v1 = fmaxf(v1, 0.0f); }
                Cmat[(size_t)row0 * N + col] = v0;
                Cmat[(size_t)(row0 + 1) * N + col] = v1;
            }
        }
    }
}

// logits[b] = mean_t(z2[b,t] @ w2.T) + b2
__global__ __launch_bounds__(256) void logits_kernel(
    const float* __restrict__ z2, const float* __restrict__ w2,
    const float* __restrict__ b2, float* __restrict__ out_logits)
{
    const int b = blockIdx.x;
    const int tid = threadIdx.x;
    const float* row = z2 + ((size_t)b * 256 + tid) * 702;
    float l0 = 0.0f, l1 = 0.0f;
    for (int i = 0; i < 702; ++i) {
        float v = row[i];
        l0 = fmaf(v, w2[i], l0);
        l1 = fmaf(v, w2[702 + i], l1);
    }
    __shared__ float s0[256], s1[256];
    s0[tid] = l0; s1[tid] = l1;
    __syncthreads();
    for (int o = 128; o; o >>= 1) {
        if (tid < o) { s0[tid] += s0[tid + o]; s1[tid] += s1[tid + o]; }
        __syncthreads();
    }
    if (tid == 0) {
        out_logits[b * 2 + 0] = s0[0] * (1.0f / 256.0f) + b2[0];
        out_logits[b * 2 + 1] = s1[0] * (1.0f / 256.0f) + b2[1];
    }
}

// out_x = x[:, 1:, :]
__global__ void x_copy_kernel(const float* __restrict__ x, float* __restrict__ out_x)
{
    int idx = blockIdx.x * blockDim.x + threadIdx.x;
    const int total = NB * (NT - 1) * NC;
    if (idx < total) {
        int bb = idx / ((NT - 1) * NC);
        out_x[idx] = x[idx + (bb + 1) * NC];
    }
}

extern "C" void kernel_launch(void* const* d_in, const int* in_sizes, int n_in,
                              void* d_out, int out_size)
{
    const float* x       = (const float*)d_in[0];
    const float* w_emb   = (const float*)d_in[1];
    const float* b_emb   = (const float*)d_in[2];
    const float* w_ih    = (const float*)d_in[3];
    const float* w_hh    = (const float*)d_in[4];
    const float* b_ih    = (const float*)d_in[5];
    const float* b_hh    = (const float*)d_in[6];
    const float* q_w0    = (const float*)d_in[7];
    const float* q_b0    = (const float*)d_in[8];
    const float* q_w1    = (const float*)d_in[9];
    const float* q_b1    = (const float*)d_in[10];
    const float* q_w2    = (const float*)d_in[11];
    const float* q_b2    = (const float*)d_in[12];
    const float* k_w0    = (const float*)d_in[13];
    const float* k_b0    = (const float*)d_in[14];
    const float* k_w1    = (const float*)d_in[15];
    const float* k_b1    = (const float*)d_in[16];
    const float* k_w2    = (const float*)d_in[17];
    const float* k_b2    = (const float*)d_in[18];
    const float* gate_bias = (const float*)d_in[19];
    const float* pred_w  = (const float*)d_in[20];
    const float* pred_b  = (const float*)d_in[21];
    const float* clf_w0  = (const float*)d_in[22];
    const float* clf_b0  = (const float*)d_in[23];
    const float* clf_w1  = (const float*)d_in[24];
    const float* clf_b1  = (const float*)d_in[25];
    const float* clf_w2  = (const float*)d_in[26];
    const float* clf_b2  = (const float*)d_in[27];

    float* out        = (float*)d_out;
    float* out_logits = out + OUT_LOGITS;
    float* out_fnc    = out + OUT_FNC;
    float* out_mix    = out + OUT_MIX;
    float* out_pred   = out + OUT_PRED;
    float* out_x      = out + OUT_X;

    cudaFuncSetAttribute(rec_kernel, cudaFuncAttributeMaxDynamicSharedMemorySize, SMEM_BYTES);

    void* z1p = nullptr;
    void* z2p = nullptr;
    cudaGetSymbolAddress(&z1p, g_z1);
    cudaGetSymbolAddress(&z2p, g_z2);
    float* z1 = (float*)z1p;
    float* z2 = (float*)z2p;

    // 0) interleave MLP weights into g_wt
    prep_wt<<<320, 256>>>(q_w0, q_w1, q_w2, k_w0, k_w1, k_w2);

    // 1) persistent recurrence: 2-CTA cluster per batch, 512 threads
    rec_kernel<<<NB * 2, NTHR, SMEM_BYTES>>>(
        x, w_emb, b_emb, w_ih, w_hh, b_ih, b_hh,
        q_b0, q_b1, q_b2, k_b0, k_b1, k_b2,
        gate_bias, pred_w, pred_b,
        out_fnc, out_mix, out_pred);

    // 2) x[:, 1:, :] copy
    {
        int total = NB * (NT - 1) * NC;
        x_copy_kernel<<<(total + 255) / 256, 256>>>(x, out_x);
    }

    // 3) classifier
    {
        dim3 grid((1404 + 63) / 64, 16384 / 128);
        gemm_relu<<<grid, 256>>>(out_mix, clf_w0, clf_b0, z1, 16384, 1404, 2809, 1);
    }
    {
        dim3 grid((702 + 63) / 64, 16384 / 128);
        gemm_relu<<<grid, 256>>>(z1, clf_w1, clf_b1, z2, 16384, 702, 1404, 1);
    }
    logits_kernel<<<NB, 256>>>(z2, clf_w2, clf_b2, out_logits);
}

// round 17
// speedup vs baseline: 1.0555x; 1.0555x over previous
#include <cuda_runtime.h>
#include <math.h>
#include <stdint.h>

// Problem constants
#define NB 64
#define NT 256
#define NC 53
#define NH 64
#define NA 128
#define NG 192
#define NCC 2809          // C*C
#define LDB_ 132          // row stride for A-wide smem buffers (mult of 4 for float4)
#define LDH_ 68           // row stride for h_gru buffer
#define LDG_ 194          // padded row stride for transposed w_hh
#define NTHR 256

// smem layout (float offsets)
#define OFF_H     0        // 27*64 = 1728
#define OFF_HG    1728     // 53*68 = 3604
#define OFF_B1    5332     // 53*132 = 6996
#define OFF_B2    12328    // 6996
#define OFF_TR    19324    // 1432
#define OFF_FNC   20756    // 1432
#define OFF_GB    22188    // 1432
#define OFF_W     23620    // 4 slots * 4096 = 16384 (16B aligned)
#define OFF_WHH   40004    // 64*194 = 12416
#define OFF_ALPHA 52420    // 192
#define OFF_BETA  52612    // 192
#define OFF_BHH   52804    // 192
#define OFF_MB0   52996    // 128
#define OFF_MB1   53124    // 128
#define OFF_MB2   53252    // 128
#define OFF_PW    53380    // 64
#define OFF_XROW  53444    // 56
#define OFF_RED   53500    // 8
#define OFF_PSUM  53516    // 2
#define OFF_SC    53518    // 2
#define SMEM_FLOATS 53520
#define SMEM_BYTES (SMEM_FLOATS * 4)   // 214,080 B

#define SLOT_STRIDE 4096   // 32 h * 128 j floats per chunk (contiguous)

// Output offsets (floats) in d_out
#define OUT_LOGITS 0
#define OUT_FNC    128
#define OUT_MIX    179904ULL
#define OUT_PRED   46202560ULL
#define OUT_X      47067520ULL

// Classifier scratch (device globals: allocation-free rule)
__device__ float g_z1[16384 * 1404]; // 92 MB
__device__ float g_z2[16384 * 702];  // 46 MB
// K-pair-interleaved MLP weights: q0(64x128), q1, q2, k0, k1, k2
// element (h, j) of layer at [hp*256 + 2*j + (h&1)], hp = h>>1
__device__ float g_wt[81920];

typedef unsigned long long u64;

__device__ __forceinline__ float sigm(float v) { return 1.0f / (1.0f + expf(-v)); }

__device__ __forceinline__ u64 pack2(float lo, float hi) {
    u64 r; asm("mov.b64 %0,{%1,%2};" : "=l"(r) : "f"(lo), "f"(hi)); return r;
}
__device__ __forceinline__ u64 bcast2(float v) { return pack2(v, v); }
__device__ __forceinline__ u64 fma2(u64 a, u64 b, u64 c) {
    u64 d; asm("fma.rn.f32x2 %0,%1,%2,%3;" : "=l"(d) : "l"(a), "l"(b), "l"(c)); return d;
}
__device__ __forceinline__ float2 unpack2(u64 v) {
    float2 f; asm("mov.b64 {%0,%1},%2;" : "=f"(f.x), "=f"(f.y) : "l"(v)); return f;
}
__device__ __forceinline__ u64 lds2(const float* p) { return *(const u64*)p; }

// ---- cluster helpers ----
__device__ __forceinline__ void cluster_sync_() {
    asm volatile("barrier.cluster.arrive.aligned;" ::: "memory");
    asm volatile("barrier.cluster.wait.aligned;" ::: "memory");
}
__device__ __forceinline__ uint32_t smem_u32(const void* p) {
    uint32_t a;
    asm("{ .reg .u64 t; cvta.to.shared.u64 t, %1; cvt.u32.u64 %0, t; }" : "=r"(a) : "l"(p));
    return a;
}
__device__ __forceinline__ uint32_t mapa32(uint32_t a, uint32_t r) {
    uint32_t o; asm("mapa.shared::cluster.u32 %0,%1,%2;" : "=r"(o) : "r"(a), "r"(r)); return o;
}
__device__ __forceinline__ u64 ld_dsmem64(uint32_t a) {
    u64 v; asm volatile("ld.shared::cluster.b64 %0, [%1];" : "=l"(v) : "r"(a)); return v;
}
__device__ __forceinline__ float ld_dsmem32(uint32_t a) {
    float v; asm volatile("ld.shared::cluster.f32 %0, [%1];" : "=f"(v) : "r"(a)); return v;
}

// ---- cp.async helpers ----
__device__ __forceinline__ void cp_async16(uint32_t dst, const void* src) {
    asm volatile("cp.async.cg.shared.global [%0], [%1], 16;" :: "r"(dst), "l"(src));
}
__device__ __forceinline__ void cp_commit() {
    asm volatile("cp.async.commit_group;" ::: "memory");
}
template<int N> __device__ __forceinline__ void cp_wait() {
    asm volatile("cp.async.wait_group %0;" :: "n"(N) : "memory");
}

// Copy one 4096-float (16KB) contiguous weight chunk into slot.
__device__ __forceinline__ void issue_chunk(uint32_t wb, const float* src, int slot, int tid) {
    uint32_t dst0 = wb + (uint32_t)(OFF_W + slot * SLOT_STRIDE) * 4u;
#pragma unroll
    for (int j = 0; j < 4; ++j) {
        int k = tid + j * NTHR;           // 0..1023 16B units
        cp_async16(dst0 + (uint32_t)(k * 16), (const char*)src + k * 16);
    }
    cp_commit();
}

// Accumulate 32 h-values of a chunk in `slot`, K-packed f32x2.
// Lane mapping: lj = lane&7 (8 j-lanes), lr = lane>>3 (4 r-lanes).
// Lane owns float4 columns #n0 and #n0+8 of its warp's 16-float4 j-slice
// (16B lane stride -> dense 128B weight wavefronts), i.e. cols c0,c0+1,c0+16,c0+17.
// Thread tile: 7 rows x 4 cols. acc[u][c]: c=0,1 -> cols c0,c0+1; c=2,3 -> c0+16,c0+17.
__device__ __forceinline__ void mlp_chunk(
    const float* sw, int slot, int in_off, int ldi, int h0,
    int n0, int rbase, u64 (&acc)[7][4])
{
    const float* wb_ = &sw[OFF_W + slot * SLOT_STRIDE + 4 * n0];
#pragma unroll
    for (int m = 0; m < 8; ++m) {
        float4 a0 = *(const float4*)(wb_ + (2 * m) * 256);        // hp 2m,   pairs lane-lj
        float4 a1 = *(const float4*)(wb_ + (2 * m) * 256 + 32);   // hp 2m,   pairs lane-lj+8
        float4 b0 = *(const float4*)(wb_ + (2 * m + 1) * 256);    // hp 2m+1
        float4 b1 = *(const float4*)(wb_ + (2 * m + 1) * 256 + 32);
        u64 wa0 = lds2((const float*)&a0), wa1 = lds2(((const float*)&a0) + 2);
        u64 wa2 = lds2((const float*)&a1), wa3 = lds2(((const float*)&a1) + 2);
        u64 wc0 = lds2((const float*)&b0), wc1 = lds2(((const float*)&b0) + 2);
        u64 wc2 = lds2((const float*)&b1), wc3 = lds2(((const float*)&b1) + 2);
        const float* inp = &sw[in_off + h0 + 4 * m];
#pragma unroll
        for (int u = 0; u < 7; ++u) {
            int r = rbase + u; if (r >= NC) r = 0;   // clamped garbage, never stored
            float4 iv = *(const float4*)(inp + r * ldi);
            u64 i01 = lds2((const float*)&iv);        // h 4m, 4m+1   (hp 2m)
            u64 i23 = lds2(((const float*)&iv) + 2);  // h 4m+2, 4m+3 (hp 2m+1)
            acc[u][0] = fma2(i01, wa0, acc[u][0]);
            acc[u][1] = fma2(i01, wa1, acc[u][1]);
            acc[u][2] = fma2(i01, wa2, acc[u][2]);
            acc[u][3] = fma2(i01, wa3, acc[u][3]);
            acc[u][0] = fma2(i23, wc0, acc[u][0]);
            acc[u][1] = fma2(i23, wc1, acc[u][1]);
            acc[u][2] = fma2(i23, wc2, acc[u][2]);
            acc[u][3] = fma2(i23, wc3, acc[u][3]);
        }
    }
}

__device__ __forceinline__ void mlp_zero(u64 (&acc)[7][4]) {
#pragma unroll
    for (int u = 0; u < 7; ++u) { acc[u][0] = 0ULL; acc[u][1] = 0ULL; acc[u][2] = 0ULL; acc[u][3] = 0ULL; }
}

__device__ __forceinline__ void mlp_store(
    float* sw, int out_off, int c0, int rbase, bool do_relu,
    u64 (&acc)[7][4], const float* bias)
{
    float b0 = bias[c0], b1 = bias[c0 + 1], b2 = bias[c0 + 16], b3 = bias[c0 + 17];
#pragma unroll
    for (int u = 0; u < 7; ++u) {
        int r = rbase + u;
        if (r >= NC) break;
        float2 p0 = unpack2(acc[u][0]);
        float2 p1 = unpack2(acc[u][1]);
        float2 p2 = unpack2(acc[u][2]);
        float2 p3 = unpack2(acc[u][3]);
        float v0 = p0.x + p0.y + b0;
        float v1 = p1.x + p1.y + b1;
        float v2 = p2.x + p2.y + b2;
        float v3 = p3.x + p3.y + b3;
        if (do_relu) {
            v0 = fmaxf(v0, 0.0f); v1 = fmaxf(v1, 0.0f);
            v2 = fmaxf(v2, 0.0f); v3 = fmaxf(v3, 0.0f);
        }
        *(float2*)&sw[out_off + r * LDB_ + c0]      = make_float2(v0, v1);
        *(float2*)&sw[out_off + r * LDB_ + c0 + 16] = make_float2(v2, v3);
    }
}

// ---- prep: K-pair-interleave MLP weights into g_wt ----
__global__ void prep_wt(
    const float* __restrict__ q_w0, const float* __restrict__ q_w1, const float* __restrict__ q_w2,
    const float* __restrict__ k_w0, const float* __restrict__ k_w1, const float* __restrict__ k_w2)
{
    int idx = blockIdx.x * blockDim.x + threadIdx.x;
    if (idx >= 81920) return;
    const float* src; int off, Kin;
    if      (idx < 8192)  { src = q_w0; off = 0;     Kin = 64;  }
    else if (idx < 24576) { src = q_w1; off = 8192;  Kin = 128; }
    else if (idx < 40960) { src = q_w2; off = 24576; Kin = 128; }
    else if (idx < 49152) { src = k_w0; off = 40960; Kin = 64;  }
    else if (idx < 65536) { src = k_w1; off = 49152; Kin = 128; }
    else                  { src = k_w2; off = 65536; Kin = 128; }
    int l = idx - off;
    int hp = l >> 8, rem = l & 255;
    int j = rem >> 1, par = rem & 1;
    int h = 2 * hp + par;
    g_wt[idx] = src[j * Kin + h];
}

// No-op spacer so ncu's captured launch slot (#4) lands on rec_kernel.
__global__ void dummy_kernel() {}

// Persistent recurrence: cluster of 2 CTAs per batch. 128 CTAs x 256 threads.
__global__ __launch_bounds__(NTHR, 1) __cluster_dims__(2, 1, 1)
void rec_kernel(
    const float* __restrict__ x,
    const float* __restrict__ w_emb, const float* __restrict__ b_emb,
    const float* __restrict__ w_ih, const float* __restrict__ w_hh,
    const float* __restrict__ b_ih, const float* __restrict__ b_hh,
    const float* __restrict__ q_b0, const float* __restrict__ q_b1, const float* __restrict__ q_b2,
    const float* __restrict__ k_b0, const float* __restrict__ k_b1, const float* __restrict__ k_b2,
    const float* __restrict__ gate_bias,
    const float* __restrict__ pred_w, const float* __restrict__ pred_b,
    float* __restrict__ out_fnc, float* __restrict__ out_mix, float* __restrict__ out_pred)
{
    extern __shared__ float sw[];
    const int tid = threadIdx.x;
    const int rank = blockIdx.x & 1;
    const int b = blockIdx.x >> 1;

    const int base = rank ? 27 : 0;
    const int cnt  = rank ? 26 : 27;
    const int baseP = rank ? 0 : 27;
    const int cntP  = rank ? 27 : 26;

    const uint32_t mybase = smem_u32(sw);
    const uint32_t peerbase = mapa32(mybase, (uint32_t)(rank ^ 1));
    const uint32_t wb = mybase;

    const int wid = tid >> 5, lane = tid & 31;

    // Interleaved weight bases for this rank's MLP path
    const float* WT  = rank ? (g_wt + 40960) : g_wt;
    const float* L0s = WT;            // 64 h rows
    const float* L1s = WT + 8192;     // 128 h rows
    const float* L2s = WT + 24576;    // 128 h rows

    const float* B0p = rank ? k_b0 : q_b0;
    const float* B1p = rank ? k_b1 : q_b1;
    const float* B2p = rank ? k_b2 : q_b2;

    // MLP thread mapping: warp grid 4j x 2r; lanes 8j x 4r; tile 7r x 4c
    const int lj = lane & 7, lr = lane >> 3;
    const int n0_mlp = 16 * (wid & 3) + lj;          // float4 index in 256-float hp row
    const int c0_mlp = 2 * n0_mlp;                   // first owned column
    const int rbase_mlp = 28 * (wid >> 2) + 7 * lr;  // {0,7,14,21, 28,35,42,49}

    // ---- one-time init ----
    if (tid < NG) {
        float a = 0.0f, be = 0.0f;
        for (int e = 0; e < NH; ++e) {
            float w = w_ih[tid * NH + e];
            a = fmaf(w, w_emb[e], a);
            be = fmaf(w, b_emb[e], be);
        }
        sw[OFF_ALPHA + tid] = a;
        sw[OFF_BETA + tid] = be + b_ih[tid];
        sw[OFF_BHH + tid] = b_hh[tid];
    }
    if (tid < NA) {
        sw[OFF_MB0 + tid] = B0p[tid];
        sw[OFF_MB1 + tid] = B1p[tid];
        sw[OFF_MB2 + tid] = B2p[tid];
    }
    if (tid < NH) sw[OFF_PW + tid] = pred_w[tid];
    if (tid < NC) sw[OFF_XROW + tid] = x[(size_t)b * NT * NC + tid];   // t = 0
    for (int idx = tid; idx < NG * NH; idx += NTHR) {
        int g = idx >> 6, hh = idx & 63;
        sw[OFF_WHH + hh * LDG_ + g] = w_hh[idx];
    }
    const int nhalf = cnt * NC;
    for (int i = tid; i < nhalf; i += NTHR) {
        sw[OFF_GB + i] = gate_bias[base * NC + i];
        sw[OFF_FNC + i] = 0.0f;
    }
    for (int i = tid; i < 27 * NH; i += NTHR) sw[OFF_H + i] = 0.0f;
    const float predb = pred_b[0];
    __syncthreads();

    for (int t = 0; t < NT; ++t) {
        // ---- prefetch next x row (register; staged to smem in gate phase) ----
        float xpref = 0.0f;
        if (t + 1 < NT && tid < NC)
            xpref = x[((size_t)b * NT + t + 1) * NC + tid];

        // ---- prefetch L0 weight chunks 0,1 (overlap with GRU) ----
        issue_chunk(wb, L0s,        0, tid);   // seq 0 -> slot 0
        issue_chunk(wb, L0s + 4096, 1, tid);   // seq 1 -> slot 1

        // ---- GRU on own half rows (j-pair packed) ----
        {
            const int jg2 = (lane & 15) * 2;     // 0..30 (+32v covers 64)
            const int rg  = (wid << 1) | (lane >> 4);  // 0..15
            const int rl0 = rg;
            const bool has1 = (rg + 16) < cnt;
            const int rl1 = has1 ? rg + 16 : 0;
            u64 ar[2][2], az[2][2], an[2][2];
#pragma unroll
            for (int v = 0; v < 2; ++v) {
                int j = jg2 + 32 * v;
                u64 br = lds2(&sw[OFF_BHH + j]);
                u64 bz = lds2(&sw[OFF_BHH + 64 + j]);
                u64 bn = lds2(&sw[OFF_BHH + 128 + j]);
                ar[0][v] = br; ar[1][v] = br;
                az[0][v] = bz; az[1][v] = bz;
                an[0][v] = bn; an[1][v] = bn;
            }
#pragma unroll 4
            for (int hh = 0; hh < NH; ++hh) {
                u64 p0 = bcast2(sw[OFF_H + rl0 * NH + hh]);
                u64 p1 = bcast2(sw[OFF_H + rl1 * NH + hh]);
                const float* wr = &sw[OFF_WHH + hh * LDG_ + jg2];
#pragma unroll
                for (int v = 0; v < 2; ++v) {
                    u64 wrv = lds2(wr + 32 * v);
                    u64 wzv = lds2(wr + 64 + 32 * v);
                    u64 wnv = lds2(wr + 128 + 32 * v);
                    ar[0][v] = fma2(p0, wrv, ar[0][v]); az[0][v] = fma2(p0, wzv, az[0][v]); an[0][v] = fma2(p0, wnv, an[0][v]);
                    ar[1][v] = fma2(p1, wrv, ar[1][v]); az[1][v] = fma2(p1, wzv, az[1][v]); an[1][v] = fma2(p1, wnv, an[1][v]);
                }
            }
#pragma unroll
            for (int u = 0; u < 2; ++u) {
                if (u == 1 && !has1) break;
                int rl = u ? rl1 : rl0;
                int rgl = base + rl;
                float xv = sw[OFF_XROW + rgl];
#pragma unroll
                for (int v = 0; v < 2; ++v) {
                    float2 Ar = unpack2(ar[u][v]);
                    float2 Az = unpack2(az[u][v]);
                    float2 An = unpack2(an[u][v]);
#pragma unroll
                    for (int e = 0; e < 2; ++e) {
                        int j = jg2 + 32 * v + e;
                        float arx = e ? Ar.y : Ar.x;
                        float azx = e ? Az.y : Az.x;
                        float anx = e ? An.y : An.x;
                        float gir = fmaf(xv, sw[OFF_ALPHA + j],       sw[OFF_BETA + j]);
                        float giz = fmaf(xv, sw[OFF_ALPHA + 64 + j],  sw[OFF_BETA + 64 + j]);
                        float gin = fmaf(xv, sw[OFF_ALPHA + 128 + j], sw[OFF_BETA + 128 + j]);
                        float rr = sigm(gir + arx);
                        float zz = sigm(giz + azx);
                        float nn = tanhf(gin + rr * anx);
                        sw[OFF_HG + rgl * LDH_ + j] = (1.0f - zz) * nn + zz * sw[OFF_H + rl * NH + j];
                    }
                }
            }
        }
        // sync #1: both halves of hg written; copy peer half
        cluster_sync_();
        {
            const uint32_t off = (uint32_t)(OFF_HG + baseP * LDH_) * 4u;
            const int n2 = cntP * (LDH_ / 2);
            for (int i = tid; i < n2; i += NTHR) {
                u64 v = ld_dsmem64(peerbase + off + 8u * (uint32_t)i);
                *(u64*)&sw[OFF_HG + baseP * LDH_ + 2 * i] = v;
            }
        }
        __syncthreads();

        // ---- own MLP: pipelined weight streaming, 10 chunks, 4-slot ring ----
        {
            u64 acc[7][4];

            // L0: seqs 0,1 (slots 0,1); in = HG (ld LDH_)
            mlp_zero(acc);
            cp_wait<1>(); __syncthreads();
            issue_chunk(wb, L1s + 0 * 4096, 2, tid);           // seq 2
            mlp_chunk(sw, 0, OFF_HG, LDH_, 0, n0_mlp, rbase_mlp, acc);
            cp_wait<1>(); __syncthreads();
            issue_chunk(wb, L1s + 1 * 4096, 3, tid);           // seq 3
            mlp_chunk(sw, 1, OFF_HG, LDH_, 32, n0_mlp, rbase_mlp, acc);
            mlp_store(sw, OFF_B1, c0_mlp, rbase_mlp, true, acc, &sw[OFF_MB0]);

            // L1: seqs 2..5 (slots 2,3,0,1); in = B1
            mlp_zero(acc);
            cp_wait<1>(); __syncthreads();                     // also orders B1 writes
            issue_chunk(wb, L1s + 2 * 4096, 0, tid);           // seq 4
            mlp_chunk(sw, 2, OFF_B1, LDB_, 0, n0_mlp, rbase_mlp, acc);
            cp_wait<1>(); __syncthreads();
            issue_chunk(wb, L1s + 3 * 4096, 1, tid);           // seq 5
            mlp_chunk(sw, 3, OFF_B1, LDB_, 32, n0_mlp, rbase_mlp, acc);
            cp_wait<1>(); __syncthreads();
            issue_chunk(wb, L2s + 0 * 4096, 2, tid);           // seq 6
            mlp_chunk(sw, 0, OFF_B1, LDB_, 64, n0_mlp, rbase_mlp, acc);
            cp_wait<1>(); __syncthreads();
            issue_chunk(wb, L2s + 1 * 4096, 3, tid);           // seq 7
            mlp_chunk(sw, 1, OFF_B1, LDB_, 96, n0_mlp, rbase_mlp, acc);
            mlp_store(sw, OFF_B2, c0_mlp, rbase_mlp, true, acc, &sw[OFF_MB1]);

            // L2: seqs 6..9 (slots 2,3,0,1); in = B2, out = B1, no relu
            mlp_zero(acc);
            cp_wait<1>(); __syncthreads();                     // also orders B2 writes
            issue_chunk(wb, L2s + 2 * 4096, 0, tid);           // seq 8
            mlp_chunk(sw, 2, OFF_B2, LDB_, 0, n0_mlp, rbase_mlp, acc);
            cp_wait<1>(); __syncthreads();
            issue_chunk(wb, L2s + 3 * 4096, 1, tid);           // seq 9
            mlp_chunk(sw, 3, OFF_B2, LDB_, 32, n0_mlp, rbase_mlp, acc);
            cp_wait<1>(); __syncthreads();
            mlp_chunk(sw, 0, OFF_B2, LDB_, 64, n0_mlp, rbase_mlp, acc);
            cp_wait<0>(); __syncthreads();
            mlp_chunk(sw, 1, OFF_B2, LDB_, 96, n0_mlp, rbase_mlp, acc);
            mlp_store(sw, OFF_B1, c0_mlp, rbase_mlp, false, acc, &sw[OFF_MB2]);
        }

        // sync #2: peer's final output ready in its B1; copy to local B2
        cluster_sync_();
        {
            const uint32_t off = (uint32_t)OFF_B1 * 4u;
            const int n2 = (NC * LDB_) / 2;  // 3498
            for (int i = tid; i < n2; i += NTHR) {
                u64 v = ld_dsmem64(peerbase + off + 8u * (uint32_t)i);
                *(u64*)&sw[OFF_B2 + 2 * i] = v;
            }
        }
        __syncthreads();

        // ---- transfer rows (own half): q[c,:] . k[d,:] over 128 ----
        {
            const int qoff = rank ? OFF_B2 : OFF_B1;
            const int koff = rank ? OFF_B1 : OFF_B2;
            const int dg = tid & 15;
            const int ry = tid >> 4;
            const int rl0 = ry;
            const bool h1 = (ry + 16) < cnt;
            const int rl1 = h1 ? ry + 16 : 0;
            int dc[4]; bool dv[4];
#pragma unroll
            for (int v = 0; v < 4; ++v) { int d = dg + 16 * v; dv[v] = d < NC; dc[v] = dv[v] ? d : 0; }
            u64 acc[2][4];
#pragma unroll
            for (int u = 0; u < 2; ++u)
#pragma unroll
                for (int v = 0; v < 4; ++v) acc[u][v] = 0ULL;
#pragma unroll 4
            for (int i = 0; i < NA; i += 2) {
                u64 q0 = lds2(&sw[qoff + (base + rl0) * LDB_ + i]);
                u64 q1 = lds2(&sw[qoff + (base + rl1) * LDB_ + i]);
#pragma unroll
                for (int v = 0; v < 4; ++v) {
                    u64 kv = lds2(&sw[koff + dc[v] * LDB_ + i]);
                    acc[0][v] = fma2(q0, kv, acc[0][v]);
                    acc[1][v] = fma2(q1, kv, acc[1][v]);
                }
            }
#pragma unroll
            for (int u = 0; u < 2; ++u) {
                if (u == 1 && !h1) break;
                int rl = u ? rl1 : rl0;
#pragma unroll
                for (int v = 0; v < 4; ++v) if (dv[v]) {
                    float2 p = unpack2(acc[u][v]);
                    sw[OFF_TR + rl * NC + dc[v]] = p.x + p.y;
                }
            }
        }
        __syncthreads();

        // ---- Frobenius norm: local partial, exchange scalar ----
        {
            float s = 0.0f;
            for (int i = tid; i < nhalf; i += NTHR) { float v = sw[OFF_TR + i]; s = fmaf(v, v, s); }
#pragma unroll
            for (int o = 16; o; o >>= 1) s += __shfl_xor_sync(0xffffffffu, s, o);
            if ((tid & 31) == 0) sw[OFF_RED + (tid >> 5)] = s;
            __syncthreads();
            if (tid == 0) {
                float tot = 0.0f;
                for (int w = 0; w < 8; ++w) tot += sw[OFF_RED + w];
                sw[OFF_PSUM] = tot;
            }
        }
        cluster_sync_();
        if (tid == 0) {
            float peer = ld_dsmem32(peerbase + (uint32_t)OFF_PSUM * 4u);
            sw[OFF_SC] = 1.0f / sqrtf(sw[OFF_PSUM] + peer);
        }
        __syncthreads();

        // ---- normalize, gate, accumulate FNC, write mix; stage next x row ----
        {
            const float rn = sw[OFF_SC];
            float* mixp = out_mix + ((size_t)b * NT + t) * NCC + base * NC;
            for (int i = tid; i < nhalf; i += NTHR) {
                float v = sw[OFF_TR + i] * rn;
                float g = sigm(fabsf(v) + sw[OFF_GB + i]);
                v *= g;
                sw[OFF_TR + i] = v;
                sw[OFF_FNC + i] += v;
                mixp[i] = v;
            }
            if (t + 1 < NT && tid < NC) sw[OFF_XROW + tid] = xpref;
        }
        __syncthreads();

        // ---- h_new (own half rows) = transfer @ h_gru(full) ----
        {
            const int hx2 = (tid & 15) * 2;
            const int ry = tid >> 4;
            const int rl0 = ry;
            const bool h1 = (ry + 16) < cnt;
            const int rl1 = h1 ? ry + 16 : 0;
            u64 acc[2][2];
            acc[0][0] = acc[0][1] = acc[1][0] = acc[1][1] = 0ULL;
#pragma unroll 4
            for (int d = 0; d < NC; ++d) {
                u64 t0 = bcast2(sw[OFF_TR + rl0 * NC + d]);
                u64 t1 = bcast2(sw[OFF_TR + rl1 * NC + d]);
#pragma unroll
                for (int v = 0; v < 2; ++v) {
                    u64 hv = lds2(&sw[OFF_HG + d * LDH_ + hx2 + 32 * v]);
                    acc[0][v] = fma2(t0, hv, acc[0][v]);
                    acc[1][v] = fma2(t1, hv, acc[1][v]);
                }
            }
#pragma unroll
            for (int u = 0; u < 2; ++u) {
                if (u == 1 && !h1) break;
                int rl = u ? rl1 : rl0;
#pragma unroll
                for (int v = 0; v < 2; ++v)
                    *(float2*)&sw[OFF_H + rl * NH + hx2 + 32 * v] = unpack2(acc[u][v]);
            }
        }
        __syncthreads();

        // ---- predicted (own half rows, t < T-1) ----
        if (t < NT - 1 && tid < cnt) {
            float a = predb;
            for (int hh = 0; hh < NH; ++hh) a = fmaf(sw[OFF_H + tid * NH + hh], sw[OFF_PW + hh], a);
            out_pred[((size_t)b * (NT - 1) + t) * NC + base + tid] = a;
        }
    }

    // ---- mean_FNC (own half rows) ----
    for (int i = tid; i < nhalf; i += NTHR)
        out_fnc[(size_t)b * NCC + base * NC + i] = sw[OFF_FNC + i] * (1.0f / 256.0f);
}

// Tiled fp32 GEMM with packed f32x2 over M-row pairs (near roofline)
#define LDAS_ 132
__global__ __launch_bounds__(256) void gemm_relu(
    const float* __restrict__ A, const float* __restrict__ W,
    const float* __restrict__ bias, float* __restrict__ Cmat,
    int M, int N, int K, int do_relu)
{
    __shared__ float As[16 * LDAS_];
    __shared__ float Ws[16][65];
    const int m0 = blockIdx.y * 128;
    const int n0 = blockIdx.x * 64;
    const int tid = threadIdx.x;
    const int tx = tid & 15, ty = tid >> 4;
    u64 acc[4][4];
#pragma unroll
    for (int u = 0; u < 4; ++u)
#pragma unroll
        for (int v = 0; v < 4; ++v) acc[u][v] = 0ULL;

    for (int k0 = 0; k0 < K; k0 += 16) {
#pragma unroll
        for (int l = 0; l < 8; ++l) {
            int idx = tid + l * 256;
            int mi = idx >> 4, kk = idx & 15;
            int k = k0 + kk;
            As[kk * LDAS_ + mi] = (k < K) ? A[(size_t)(m0 + mi) * K + k] : 0.0f;
        }
#pragma unroll
        for (int l = 0; l < 4; ++l) {
            int idx = tid + l * 256;
            int ni = idx >> 4, kk = idx & 15;
            int k = k0 + kk, n = n0 + ni;
            Ws[kk][ni] = (k < K && n < N) ? W[(size_t)n * K + k] : 0.0f;
        }
        __syncthreads();
#pragma unroll
        for (int kk = 0; kk < 16; ++kk) {
            u64 a2[4], w2[4];
#pragma unroll
            for (int u = 0; u < 4; ++u) a2[u] = lds2(&As[kk * LDAS_ + 2 * ty + 32 * u]);
#pragma unroll
            for (int v = 0; v < 4; ++v) w2[v] = bcast2(Ws[kk][tx + 16 * v]);
#pragma unroll
            for (int u = 0; u < 4; ++u)
#pragma unroll
                for (int v = 0; v < 4; ++v) acc[u][v] = fma2(a2[u], w2[v], acc[u][v]);
        }
        __syncthreads();
    }
#pragma unroll
    for (int u = 0; u < 4; ++u) {
        int row0 = m0 + 2 * ty + 32 * u;
#pragma unroll
        for (int v = 0; v < 4; ++v) {
            int col = n0 + tx + 16 * v;
            if (col < N) {
                float2 p = unpack2(acc[u][v]);
                float bb = bias[col];
                float v0 = p.x + bb, v1 = p.y + bb;
                if (do_relu) { v0 = fmaxf(v0, 0.0f); v1 = fmaxf(v1, 0.0f); }
                Cmat[(size_t)row0 * N + col] = v0;
                Cmat[(size_t)(row0 + 1) * N + col] = v1;
            }
        }
    }
}

// logits[b] = mean_t(z2[b,t] @ w2.T) + b2
__global__ __launch_bounds__(256) void logits_kernel(
    const float* __restrict__ z2, const float* __restrict__ w2,
    const float* __restrict__ b2, float* __restrict__ out_logits)
{
    const int b = blockIdx.x;
    const int tid = threadIdx.x;
    const float* row = z2 + ((size_t)b * 256 + tid) * 702;
    float l0 = 0.0f, l1 = 0.0f;
    for (int i = 0; i < 702; ++i) {
        float v = row[i];
        l0 = fmaf(v, w2[i], l0);
        l1 = fmaf(v, w2[702 + i], l1);
    }
    __shared__ float s0[256], s1[256];
    s0[tid] = l0; s1[tid] = l1;
    __syncthreads();
    for (int o = 128; o; o >>= 1) {
        if (tid < o) { s0[tid] += s0[tid + o]; s1[tid] += s1[tid + o]; }
        __syncthreads();
    }
    if (tid == 0) {
        out_logits[b * 2 + 0] = s0[0] * (1.0f / 256.0f) + b2[0];
        out_logits[b * 2 + 1] = s1[0] * (1.0f / 256.0f) + b2[1];
    }
}

// out_x = x[:, 1:, :]
__global__ void x_copy_kernel(const float* __restrict__ x, float* __restrict__ out_x)
{
    int idx = blockIdx.x * blockDim.x + threadIdx.x;
    const int total = NB * (NT - 1) * NC;
    if (idx < total) {
        int bb = idx / ((NT - 1) * NC);
        out_x[idx] = x[idx + (bb + 1) * NC];
    }
}

extern "C" void kernel_launch(void* const* d_in, const int* in_sizes, int n_in,
                              void* d_out, int out_size)
{
    const float* x       = (const float*)d_in[0];
    const float* w_emb   = (const float*)d_in[1];
    const float* b_emb   = (const float*)d_in[2];
    const float* w_ih    = (const float*)d_in[3];
    const float* w_hh    = (const float*)d_in[4];
    const float* b_ih    = (const float*)d_in[5];
    const float* b_hh    = (const float*)d_in[6];
    const float* q_w0    = (const float*)d_in[7];
    const float* q_b0    = (const float*)d_in[8];
    const float* q_w1    = (const float*)d_in[9];
    const float* q_b1    = (const float*)d_in[10];
    const float* q_w2    = (const float*)d_in[11];
    const float* q_b2    = (const float*)d_in[12];
    const float* k_w0    = (const float*)d_in[13];
    const float* k_b0    = (const float*)d_in[14];
    const float* k_w1    = (const float*)d_in[15];
    const float* k_b1    = (const float*)d_in[16];
    const float* k_w2    = (const float*)d_in[17];
    const float* k_b2    = (const float*)d_in[18];
    const float* gate_bias = (const float*)d_in[19];
    const float* pred_w  = (const float*)d_in[20];
    const float* pred_b  = (const float*)d_in[21];
    const float* clf_w0  = (const float*)d_in[22];
    const float* clf_b0  = (const float*)d_in[23];
    const float* clf_w1  = (const float*)d_in[24];
    const float* clf_b1  = (const float*)d_in[25];
    const float* clf_w2  = (const float*)d_in[26];
    const float* clf_b2  = (const float*)d_in[27];

    float* out        = (float*)d_out;
    float* out_logits = out + OUT_LOGITS;
    float* out_fnc    = out + OUT_FNC;
    float* out_mix    = out + OUT_MIX;
    float* out_pred   = out + OUT_PRED;
    float* out_x      = out + OUT_X;

    cudaFuncSetAttribute(rec_kernel, cudaFuncAttributeMaxDynamicSharedMemorySize, SMEM_BYTES);

    void* z1p = nullptr;
    void* z2p = nullptr;
    cudaGetSymbolAddress(&z1p, g_z1);
    cudaGetSymbolAddress(&z2p, g_z2);
    float* z1 = (float*)z1p;
    float* z2 = (float*)z2p;

    // Launch order arranged so ncu's captured slot (4th launch) is rec_kernel.
    // 1) interleave MLP weights into g_wt
    prep_wt<<<320, 256>>>(q_w0, q_w1, q_w2, k_w0, k_w1, k_w2);

    // 2) x[:, 1:, :] copy (independent of rec)
    {
        int total = NB * (NT - 1) * NC;
        x_copy_kernel<<<(total + 255) / 256, 256>>>(x, out_x);
    }

    // 3) spacer
    dummy_kernel<<<1, 32>>>();

    // 4) persistent recurrence: 2-CTA cluster per batch, 256 threads
    rec_kernel<<<NB * 2, NTHR, SMEM_BYTES>>>(
        x, w_emb, b_emb, w_ih, w_hh, b_ih, b_hh,
        q_b0, q_b1, q_b2, k_b0, k_b1, k_b2,
        gate_bias, pred_w, pred_b,
        out_fnc, out_mix, out_pred);

    // 5-7) classifier
    {
        dim3 grid((1404 + 63) / 64, 16384 / 128);
        gemm_relu<<<grid, 256>>>(out_mix, clf_w0, clf_b0, z1, 16384, 1404, 2809, 1);
    }
    {
        dim3 grid((702 + 63) / 64, 16384 / 128);
        gemm_relu<<<grid, 256>>>(z1, clf_w1, clf_b1, z2, 16384, 702, 1404, 1);
    }
    logits_kernel<<<NB, 256>>>(z2, clf_w2, clf_b2, out_logits);
}